// round 3
// baseline (speedup 1.0000x reference)
#include <cuda_runtime.h>
#include <math.h>

#define NSEQ 2048
#define BATCH 2
#define NHEAD 16
#define MROWS 4096
#define ASCALE 0.125f

typedef unsigned long long u64;
struct P3 { const float* a; const float* b; const float* c; };
__device__ __forceinline__ const float* sel(P3 p, int i) {
    return i == 0 ? p.a : (i == 1 ? p.b : p.c);
}

__device__ __forceinline__ u64 PK2(float lo, float hi) {
    u64 r; asm("mov.b64 %0,{%1,%2};" : "=l"(r) : "f"(lo), "f"(hi)); return r;
}
__device__ __forceinline__ u64 DUP(float v) { return PK2(v, v); }
__device__ __forceinline__ void FMA2(u64& d, u64 a, u64 b) {
    asm("fma.rn.f32x2 %0,%1,%2,%0;" : "+l"(d) : "l"(a), "l"(b));
}
__device__ __forceinline__ void MUL2(u64& d, u64 a) {
    asm("mul.rn.f32x2 %0,%0,%1;" : "+l"(d) : "l"(a));
}
__device__ __forceinline__ float2 UPK(u64 v) {
    float2 f; asm("mov.b64 {%0,%1},%2;" : "=f"(f.x), "=f"(f.y) : "l"(v)); return f;
}

// ---------------- scratch ----------------
__device__ float g_t[3 * MROWS * 64];
__device__ float g_l[3 * MROWS * 4];
__device__ float g_qkv[3 * BATCH * NHEAD * NSEQ * 64];
__device__ float g_comb[BATCH * NHEAD * NSEQ * 64];

// ---------------------------------------------------------------------------
// t = x @ U * alpha.  64x64 tile, 128 thr, 8x4 micro, Kc=64, z-fused over 3.
// ---------------------------------------------------------------------------
__global__ __launch_bounds__(128) void k_xu(const float* __restrict__ X,
                                            P3 Us, P3 als, float* __restrict__ Tb) {
    __shared__ float a_s[64][68];
    __shared__ float b_s[64][68];
    int p = blockIdx.y;
    const float* U = sel(Us, p);
    const float* alpha = sel(als, p);
    float* T = Tb + (size_t)p * MROWS * 64;
    int t = threadIdx.x;
    int m0 = blockIdx.x * 64;
    int tm = t >> 4, tn4 = t & 15;
    u64 acc2[8][2] = {};
    for (int k0 = 0; k0 < 1024; k0 += 64) {
#pragma unroll
        for (int rep = 0; rep < 8; rep++) {
            int fidx = t + rep * 128;
            int m = fidx >> 4, kq = fidx & 15;
            float4 v = *(const float4*)&X[(size_t)(m0 + m) * 1024 + k0 + kq * 4];
            a_s[kq * 4 + 0][m] = v.x; a_s[kq * 4 + 1][m] = v.y;
            a_s[kq * 4 + 2][m] = v.z; a_s[kq * 4 + 3][m] = v.w;
        }
#pragma unroll
        for (int rep = 0; rep < 8; rep++) {
            int fidx = t + rep * 128;
            int kk = fidx >> 4, nq = fidx & 15;
            *(float4*)&b_s[kk][nq * 4] = *(const float4*)&U[(size_t)(k0 + kk) * 64 + nq * 4];
        }
        __syncthreads();
#pragma unroll 8
        for (int kk = 0; kk < 64; kk++) {
            float4 a0 = *(const float4*)&a_s[kk][tm * 8];
            float4 a1 = *(const float4*)&a_s[kk][tm * 8 + 4];
            ulonglong2 bp = *(const ulonglong2*)&b_s[kk][tn4 * 4];
            float aa[8] = {a0.x, a0.y, a0.z, a0.w, a1.x, a1.y, a1.z, a1.w};
#pragma unroll
            for (int i = 0; i < 8; i++) {
                u64 d = DUP(aa[i]);
                FMA2(acc2[i][0], d, bp.x);
                FMA2(acc2[i][1], d, bp.y);
            }
        }
        __syncthreads();
    }
    float al0 = alpha[tn4 * 4 + 0], al1 = alpha[tn4 * 4 + 1];
    float al2 = alpha[tn4 * 4 + 2], al3 = alpha[tn4 * 4 + 3];
#pragma unroll
    for (int i = 0; i < 8; i++) {
        float2 c0 = UPK(acc2[i][0]), c1 = UPK(acc2[i][1]);
        float4 o = make_float4(c0.x * al0, c0.y * al1, c1.x * al2, c1.y * al3);
        *(float4*)&T[(size_t)(m0 + tm * 8 + i) * 64 + tn4 * 4] = o;
    }
}

// ---------------------------------------------------------------------------
// l = x @ A, all 3 projections (12 cols) in one pass over x.
// ---------------------------------------------------------------------------
__global__ __launch_bounds__(128) void k_lora(const float* __restrict__ X,
                                              P3 As, float* __restrict__ Lb) {
    int m = blockIdx.x;
    int t = threadIdx.x;
    float p[12] = {};
    const float* A0 = As.a; const float* A1 = As.b; const float* A2 = As.c;
    for (int k = t; k < 1024; k += 128) {
        float xv = X[(size_t)m * 1024 + k];
#pragma unroll
        for (int j = 0; j < 4; j++) {
            p[j]     += xv * A0[k * 4 + j];
            p[4 + j] += xv * A1[k * 4 + j];
            p[8 + j] += xv * A2[k * 4 + j];
        }
    }
    __shared__ float red[12][128];
#pragma unroll
    for (int j = 0; j < 12; j++) red[j][t] = p[j];
    __syncthreads();
    for (int s = 64; s > 0; s >>= 1) {
        if (t < s) {
#pragma unroll
            for (int j = 0; j < 12; j++) red[j][t] += red[j][t + s];
        }
        __syncthreads();
    }
    if (t < 12) {
        int pr = t >> 2, j = t & 3;
        Lb[(size_t)pr * MROWS * 4 + (size_t)m * 4 + j] = red[t][0];
    }
}

// ---------------------------------------------------------------------------
// proj: out = [t | l] @ [V^T ; Blora] + bias -> [B,H,N,HD].
// 128m x 128n tile, K=68 single chunk, 256 thr, 8x8 micro. z-fused over 3.
// ---------------------------------------------------------------------------
__global__ __launch_bounds__(256) void k_proj(const float* __restrict__ Tb,
                                              const float* __restrict__ Lb,
                                              P3 Vs, P3 Bls, P3 bis,
                                              float* __restrict__ QKV) {
    __shared__ float a_s[68][132];
    __shared__ float b_s[68][132];
    int p = blockIdx.z;
    const float* T = Tb + (size_t)p * MROWS * 64;
    const float* L = Lb + (size_t)p * MROWS * 4;
    const float* V = sel(Vs, p);
    const float* Blora = sel(Bls, p);
    const float* bias = sel(bis, p);
    float* O = QKV + (size_t)p * BATCH * NHEAD * NSEQ * 64;

    int t = threadIdx.x;
    int m0 = blockIdx.x * 128;
    int n0 = blockIdx.y * 128;
    int tq = t >> 4, tn = t & 15;

#pragma unroll
    for (int rep = 0; rep < 8; rep++) {           // T[m][k] -> a_s[k][m]
        int fidx = t + rep * 256;
        int m = fidx >> 4, kq = fidx & 15;
        float4 v = *(const float4*)&T[(size_t)(m0 + m) * 64 + kq * 4];
        a_s[kq * 4 + 0][m] = v.x; a_s[kq * 4 + 1][m] = v.y;
        a_s[kq * 4 + 2][m] = v.z; a_s[kq * 4 + 3][m] = v.w;
    }
    if (t < 128) {                                // lora rows 64..67
        float4 lv = *(const float4*)&L[(size_t)(m0 + t) * 4];
        a_s[64][t] = lv.x; a_s[65][t] = lv.y; a_s[66][t] = lv.z; a_s[67][t] = lv.w;
    }
#pragma unroll
    for (int rep = 0; rep < 8; rep++) {           // V[n][k] -> b_s[k][n]
        int fidx = t + rep * 256;
        int n = fidx >> 4, kq = fidx & 15;
        float4 v = *(const float4*)&V[(size_t)(n0 + n) * 64 + kq * 4];
        b_s[kq * 4 + 0][n] = v.x; b_s[kq * 4 + 1][n] = v.y;
        b_s[kq * 4 + 2][n] = v.z; b_s[kq * 4 + 3][n] = v.w;
    }
#pragma unroll
    for (int rep = 0; rep < 2; rep++) {           // Blora rows 64..67
        int idx = t + rep * 256;
        int j = idx >> 7, n = idx & 127;
        b_s[64 + j][n] = Blora[(size_t)j * 1024 + n0 + n];
    }
    __syncthreads();

    u64 acc2[8][4] = {};
#pragma unroll 4
    for (int kk = 0; kk < 68; kk++) {
        float4 a0 = *(const float4*)&a_s[kk][tq * 8];
        float4 a1 = *(const float4*)&a_s[kk][tq * 8 + 4];
        ulonglong2 bp0 = *(const ulonglong2*)&b_s[kk][tn * 8];
        ulonglong2 bp1 = *(const ulonglong2*)&b_s[kk][tn * 8 + 4];
        float aa[8] = {a0.x, a0.y, a0.z, a0.w, a1.x, a1.y, a1.z, a1.w};
#pragma unroll
        for (int i = 0; i < 8; i++) {
            u64 d = DUP(aa[i]);
            FMA2(acc2[i][0], d, bp0.x); FMA2(acc2[i][1], d, bp0.y);
            FMA2(acc2[i][2], d, bp1.x); FMA2(acc2[i][3], d, bp1.y);
        }
    }

    int ng = n0 + tn * 8;
    int h = ng >> 6, hd0 = ng & 63;
    float bb[8];
#pragma unroll
    for (int j = 0; j < 8; j++) bb[j] = bias[ng + j];
#pragma unroll
    for (int i = 0; i < 8; i++) {
        int m = m0 + tq * 8 + i;
        int bi = m >> 11, ni = m & 2047;
        size_t base = ((size_t)(bi * 16 + h) * 2048 + ni) * 64 + hd0;
        float2 c0 = UPK(acc2[i][0]), c1 = UPK(acc2[i][1]);
        float2 c2 = UPK(acc2[i][2]), c3 = UPK(acc2[i][3]);
        float4 o0 = make_float4(c0.x + bb[0], c0.y + bb[1], c1.x + bb[2], c1.y + bb[3]);
        float4 o1 = make_float4(c2.x + bb[4], c2.y + bb[5], c3.x + bb[6], c3.y + bb[7]);
        *(float4*)&O[base + 0] = o0;
        *(float4*)&O[base + 4] = o1;
    }
}

// ---------------------------------------------------------------------------
// fused 3-branch flash attention. BQ=128, BK=128, 256 thr.
// QK: 8q x 8k per thread (pairs along q). PV: 8q x 4hd (pairs along hd).
// phases: 0=local(win 128), 1=glob(32 strided), 2=rag(256 mem).
// per-phase result accumulated into O (g_comb).
// ---------------------------------------------------------------------------
__global__ __launch_bounds__(256) void k_attn_all(const float* __restrict__ Q,
                                                  const float* __restrict__ K,
                                                  const float* __restrict__ V,
                                                  const float* __restrict__ MEMV,
                                                  float* __restrict__ O) {
    extern __shared__ float sm[];
    float* q_s = sm;              // [64 hd][132] (128 q)
    float* k_s = sm + 8448;       // [64 hd][132] (128 k)
    float* v_s = sm + 16896;      // [128 k][68]  (64 hd)
    float* p_s = sm + 25600;      // [128 k][132] (128 q)
    __shared__ float mrow[128], lrow[128], fac[128];

    int t = threadIdx.x;
    int qt = blockIdx.x;          // 0..15
    int h = blockIdx.y;
    int b = blockIdx.z;
    int q0 = qt * 128;
    int tq = t >> 4;              // 0..15 : 8 q rows
    int tk = t & 15;              // 0..15 : QK 8 interleaved k / PV 4 hd
    size_t qbase = ((size_t)(b * 16 + h) * 2048 + q0) * 64;

#pragma unroll
    for (int rep = 0; rep < 8; rep++) {
        int fidx = t + rep * 256;
        int q = fidx >> 4, hq = fidx & 15;
        float4 v = *(const float4*)&Q[qbase + (size_t)q * 64 + hq * 4];
        q_s[(hq * 4 + 0) * 132 + q] = v.x; q_s[(hq * 4 + 1) * 132 + q] = v.y;
        q_s[(hq * 4 + 2) * 132 + q] = v.z; q_s[(hq * 4 + 3) * 132 + q] = v.w;
    }

    for (int ph = 0; ph < 3; ph++) {
        __syncthreads();
        if (t < 128) { mrow[t] = -1e30f; lrow[t] = 0.f; }
        u64 acc2[8][2] = {};
        int c_lo, c_hi;
        if (ph == 0) { c_lo = (qt == 0) ? 0 : -1; c_hi = (qt == 15) ? 0 : 1; }
        else if (ph == 1) { c_lo = 0; c_hi = 0; }
        else { c_lo = 0; c_hi = 1; }

        for (int c = c_lo; c <= c_hi; c++) {
            int klen = (ph == 1) ? 32 : 128;
            int key0 = (ph == 0) ? q0 + c * 128 : c * 128;
            __syncthreads();
#pragma unroll
            for (int rep = 0; rep < 8; rep++) {
                int fidx = t + rep * 256;
                int kk = fidx >> 4, hq = fidx & 15;
                bool valid = (ph != 1) || (kk < 32);
                size_t rowoff;
                const float *Ks, *Vs;
                if (ph == 2) {
                    rowoff = ((size_t)b * 256 + key0 + kk) * 64;
                    Ks = MEMV; Vs = MEMV;
                } else {
                    int krow = (ph == 0) ? key0 + kk : kk * 64;
                    rowoff = ((size_t)(b * 16 + h) * 2048 + (valid ? krow : 0)) * 64;
                    Ks = K; Vs = V;
                }
                float4 kv = valid ? *(const float4*)&Ks[rowoff + hq * 4] : make_float4(0, 0, 0, 0);
                float4 vv = valid ? *(const float4*)&Vs[rowoff + hq * 4] : make_float4(0, 0, 0, 0);
                k_s[(hq * 4 + 0) * 132 + kk] = kv.x; k_s[(hq * 4 + 1) * 132 + kk] = kv.y;
                k_s[(hq * 4 + 2) * 132 + kk] = kv.z; k_s[(hq * 4 + 3) * 132 + kk] = kv.w;
                *(float4*)&v_s[kk * 68 + hq * 4] = vv;
            }
            __syncthreads();

            // ---- QK^T ----
            {
                u64 sc2[8][4] = {};
#pragma unroll 8
                for (int hd = 0; hd < 64; hd++) {
                    ulonglong2 qp0 = *(const ulonglong2*)&q_s[hd * 132 + tq * 8];
                    ulonglong2 qp1 = *(const ulonglong2*)&q_s[hd * 132 + tq * 8 + 4];
#pragma unroll
                    for (int j = 0; j < 8; j++) {
                        u64 kd = DUP(k_s[hd * 132 + tk + 16 * j]);
                        FMA2(sc2[j][0], kd, qp0.x); FMA2(sc2[j][1], kd, qp0.y);
                        FMA2(sc2[j][2], kd, qp1.x); FMA2(sc2[j][3], kd, qp1.y);
                    }
                }
#pragma unroll
                for (int j = 0; j < 8; j++) {
                    int kl = tk + 16 * j;
                    int gk = key0 + kl;
#pragma unroll
                    for (int p2 = 0; p2 < 4; p2++) {
                        float2 s = UPK(sc2[j][p2]);
                        int gq = q0 + tq * 8 + p2 * 2;
                        bool ok0, ok1;
                        if (ph == 0) {
                            int d0 = gq - gk; if (d0 < 0) d0 = -d0;
                            int d1 = gq + 1 - gk; if (d1 < 0) d1 = -d1;
                            ok0 = d0 <= 128; ok1 = d1 <= 128;
                        } else if (ph == 1) { ok0 = ok1 = (kl < 32); }
                        else { ok0 = ok1 = true; }
                        float v0 = ok0 ? s.x * ASCALE : -1e30f;
                        float v1 = ok1 ? s.y * ASCALE : -1e30f;
                        *(u64*)&p_s[kl * 132 + tq * 8 + p2 * 2] = PK2(v0, v1);
                    }
                }
            }
            __syncthreads();

            // ---- online softmax: 128 rows x 2 threads ----
            {
                int r = t >> 1, half = t & 1;
                float om = mrow[r];
                float mx = om;
                for (int m = half; m < klen; m += 2)
                    mx = fmaxf(mx, p_s[m * 132 + r]);
                mx = fmaxf(mx, __shfl_xor_sync(0xffffffffu, mx, 1));
                float sum = 0.f;
                for (int m = half; m < klen; m += 2) {
                    float e = __expf(p_s[m * 132 + r] - mx);
                    p_s[m * 132 + r] = e;
                    sum += e;
                }
                sum += __shfl_xor_sync(0xffffffffu, sum, 1);
                if (half == 0) {
                    float f = __expf(om - mx);
                    lrow[r] = lrow[r] * f + sum;
                    mrow[r] = mx;
                    fac[r] = f;
                }
            }
            __syncthreads();

            // ---- rescale + PV ----
            {
#pragma unroll
                for (int i = 0; i < 8; i++) {
                    u64 fd = DUP(fac[tq * 8 + i]);
                    MUL2(acc2[i][0], fd);
                    MUL2(acc2[i][1], fd);
                }
#pragma unroll 4
                for (int kk = 0; kk < klen; kk++) {
                    float4 pa = *(const float4*)&p_s[kk * 132 + tq * 8];
                    float4 pb = *(const float4*)&p_s[kk * 132 + tq * 8 + 4];
                    ulonglong2 vp = *(const ulonglong2*)&v_s[kk * 68 + tk * 4];
                    float pp[8] = {pa.x, pa.y, pa.z, pa.w, pb.x, pb.y, pb.z, pb.w};
#pragma unroll
                    for (int i = 0; i < 8; i++) {
                        u64 d = DUP(pp[i]);
                        FMA2(acc2[i][0], d, vp.x);
                        FMA2(acc2[i][1], d, vp.y);
                    }
                }
            }
        }

        // ---- normalize + accumulate into O ----
#pragma unroll
        for (int i = 0; i < 8; i++) {
            float l = lrow[tq * 8 + i];
            float inv = (l > 0.f) ? 1.f / l : 0.f;
            float2 a0 = UPK(acc2[i][0]), a1 = UPK(acc2[i][1]);
            size_t off = qbase + (size_t)(tq * 8 + i) * 64 + tk * 4;
            float4 o = make_float4(a0.x * inv, a0.y * inv, a1.x * inv, a1.y * inv);
            if (ph != 0) {
                float4 pr = *(const float4*)&O[off];
                o.x += pr.x; o.y += pr.y; o.z += pr.z; o.w += pr.w;
            }
            *(float4*)&O[off] = o;
        }
    }
}

// ---------------------------------------------------------------------------
// out = fused @ out_W^T + out_b.  128x128 tile, Kc=16, 8x8 micro, f32x2.
// ---------------------------------------------------------------------------
__global__ __launch_bounds__(256) void k_outproj(const float* __restrict__ C,
                                                 const float* __restrict__ W,
                                                 const float* __restrict__ bias,
                                                 float* __restrict__ out) {
    __shared__ float a_s[16][132];
    __shared__ float b_s[16][132];
    int t = threadIdx.x;
    int m0 = blockIdx.x * 128, n0 = blockIdx.y * 128;
    int tq = t & 15, tn = t >> 4;
    u64 acc2[8][4] = {};
    for (int k0 = 0; k0 < 1024; k0 += 16) {
        int hblk = k0 >> 6;
#pragma unroll
        for (int rep = 0; rep < 2; rep++) {
            int fidx = t + rep * 256;
            int m = fidx >> 2, kq = fidx & 3;
            int mg = m0 + m;
            int bi = mg >> 11, ni = mg & 2047;
            int kg = k0 + kq * 4;
            float4 v = *(const float4*)&C[((size_t)(bi * 16 + hblk) * 2048 + ni) * 64 + (kg & 63)];
            a_s[kq * 4 + 0][m] = v.x; a_s[kq * 4 + 1][m] = v.y;
            a_s[kq * 4 + 2][m] = v.z; a_s[kq * 4 + 3][m] = v.w;
        }
#pragma unroll
        for (int rep = 0; rep < 2; rep++) {
            int fidx = t + rep * 256;
            int n = fidx >> 2, kq = fidx & 3;
            float4 v = *(const float4*)&W[(size_t)(n0 + n) * 1024 + k0 + kq * 4];
            b_s[kq * 4 + 0][n] = v.x; b_s[kq * 4 + 1][n] = v.y;
            b_s[kq * 4 + 2][n] = v.z; b_s[kq * 4 + 3][n] = v.w;
        }
        __syncthreads();
#pragma unroll
        for (int kk = 0; kk < 16; kk++) {
            float4 a0 = *(const float4*)&a_s[kk][tq * 8];
            float4 a1 = *(const float4*)&a_s[kk][tq * 8 + 4];
            ulonglong2 bp0 = *(const ulonglong2*)&b_s[kk][tn * 8];
            ulonglong2 bp1 = *(const ulonglong2*)&b_s[kk][tn * 8 + 4];
            float aa[8] = {a0.x, a0.y, a0.z, a0.w, a1.x, a1.y, a1.z, a1.w};
#pragma unroll
            for (int i = 0; i < 8; i++) {
                u64 d = DUP(aa[i]);
                FMA2(acc2[i][0], d, bp0.x); FMA2(acc2[i][1], d, bp0.y);
                FMA2(acc2[i][2], d, bp1.x); FMA2(acc2[i][3], d, bp1.y);
            }
        }
        __syncthreads();
    }
#pragma unroll
    for (int i = 0; i < 8; i++) {
        int m = m0 + tq * 8 + i;
#pragma unroll
        for (int jq = 0; jq < 2; jq++) {
            float2 c0 = UPK(acc2[i][jq * 2 + 0]);
            float2 c1 = UPK(acc2[i][jq * 2 + 1]);
            float4 o;
            o.x = c0.x + bias[n0 + tn * 8 + jq * 4 + 0];
            o.y = c0.y + bias[n0 + tn * 8 + jq * 4 + 1];
            o.z = c1.x + bias[n0 + tn * 8 + jq * 4 + 2];
            o.w = c1.y + bias[n0 + tn * 8 + jq * 4 + 3];
            *(float4*)&out[(size_t)m * 1024 + n0 + tn * 8 + jq * 4] = o;
        }
    }
}

// ---------------------------------------------------------------------------
__global__ __launch_bounds__(128) void k_heads(const float* __restrict__ C,
                                               const float* __restrict__ tW, const float* __restrict__ tb,
                                               const float* __restrict__ iW, const float* __restrict__ ib,
                                               const float* __restrict__ cW, const float* __restrict__ cb,
                                               float* __restrict__ out) {
    int r = blockIdx.x;
    int b = r >> 11, n = r & 2047;
    __shared__ float last[64];
    int t = threadIdx.x;
    if (t < 64) last[t] = C[((size_t)(b * 16) * 2048 + n) * 64 + t];
    __syncthreads();
    if (t < 2) {
        float s = tb[t];
        for (int k = 0; k < 64; k++) s += last[k] * tW[t * 64 + k];
        out[4194304 + (size_t)r * 2 + t] = s;
    } else if (t < 66) {
        int j = t - 2;
        float s = ib[j];
        for (int k = 0; k < 64; k++) s += last[k] * iW[j * 64 + k];
        out[4202496 + (size_t)r * 64 + j] = s;
    } else if (t < 98) {
        int j = t - 66;
        float s = cb[j];
        for (int k = 0; k < 64; k++) s += last[k] * cW[j * 64 + k];
        out[4464640 + (size_t)r * 32 + j] = s;
    }
}

// ---------------------------------------------------------------------------
extern "C" void kernel_launch(void* const* d_in, const int* in_sizes, int n_in,
                              void* d_out, int out_size) {
    const float* x   = (const float*)d_in[0];
    const float* mem = (const float*)d_in[1];
    P3 Us  = { (const float*)d_in[2],  (const float*)d_in[8],  (const float*)d_in[14] };
    P3 Vs  = { (const float*)d_in[3],  (const float*)d_in[9],  (const float*)d_in[15] };
    P3 als = { (const float*)d_in[4],  (const float*)d_in[10], (const float*)d_in[16] };
    P3 As  = { (const float*)d_in[5],  (const float*)d_in[11], (const float*)d_in[17] };
    P3 Bls = { (const float*)d_in[6],  (const float*)d_in[12], (const float*)d_in[18] };
    P3 bis = { (const float*)d_in[7],  (const float*)d_in[13], (const float*)d_in[19] };
    const float* outW = (const float*)d_in[20];
    const float* outb = (const float*)d_in[21];
    const float* tW = (const float*)d_in[22];
    const float* tb = (const float*)d_in[23];
    const float* iW = (const float*)d_in[24];
    const float* ib = (const float*)d_in[25];
    const float* cW = (const float*)d_in[26];
    const float* cb = (const float*)d_in[27];
    float* out = (float*)d_out;

    void *pT, *pL, *pQKV, *pC;
    cudaGetSymbolAddress(&pT, g_t);
    cudaGetSymbolAddress(&pL, g_l);
    cudaGetSymbolAddress(&pQKV, g_qkv);
    cudaGetSymbolAddress(&pC, g_comb);
    float* Tb = (float*)pT;
    float* Lb = (float*)pL;
    float* QKV = (float*)pQKV;
    float* Cb = (float*)pC;
    const size_t QSZ = (size_t)BATCH * NHEAD * NSEQ * 64;

    k_xu<<<dim3(64, 3), 128>>>(x, Us, als, Tb);
    k_lora<<<4096, 128>>>(x, As, Lb);
    k_proj<<<dim3(32, 8, 3), 256>>>(Tb, Lb, Vs, Bls, bis, QKV);

    const int SMEM_ATTN = 42496 * 4;  // 169984 B
    cudaFuncSetAttribute(k_attn_all, cudaFuncAttributeMaxDynamicSharedMemorySize, SMEM_ATTN);
    k_attn_all<<<dim3(16, 16, 2), 256, SMEM_ATTN>>>(QKV, QKV + QSZ, QKV + 2 * QSZ, mem, Cb);

    k_outproj<<<dim3(32, 8), 256>>>(Cb, outW, outb, out);
    k_heads<<<4096, 128>>>(Cb, tW, tb, iW, ib, cW, cb, out);
}